// round 16
// baseline (speedup 1.0000x reference)
#include <cuda_runtime.h>
#include <cuda_bf16.h>
#include <cuda_fp16.h>
#include <math.h>

// Problem constants
#define NN   50000
#define EE   800000
#define NMOL 2000
#define INRR 64
#define OUTD 128
#define EDD  16
#define CLSD 256
#define HSW  640   // OUT*(L_CONV+1)

// Static scratch (no allocations allowed)
__device__ float g_agg[(size_t)NN * 128];
__device__ float g_h0[(size_t)NN * 128];
__device__ float g_HS[(size_t)NN * HSW];
__device__ float g_pool[(size_t)NMOL * 128];
__device__ float g_z1[(size_t)NN * CLSD];
__device__ float g_z2[(size_t)NN * CLSD];
// CSR (by dst) — g_cnt zero at load; csr_scan re-zeroes it each call.
__device__ int g_cnt[NN];
__device__ int g_off[NN + 1];
__device__ int g_cur[NN];
__device__ int g_srcs[EE];                       // CSR-ordered src node
__device__ float g_attrs[(size_t)EE * 16];       // CSR-ordered edge_attr
__device__ __half g_emat[(size_t)EE * 128];      // per-layer edge MLP outputs (fp16)

// Pre-converted packed bf16 weights (hi/lo split), word(kp,m)=pack(B[2kp][m],B[2kp+1][m])
#define WC1_OFF   0                 // conv1W:  Kp=32,  M=128 -> 4096
#define WCV_OFF   4096              // convW i: Kp=64,  M=128 -> 8192 each (x4)
#define WK1_OFF   36864             // cls1W:   Kp=320, M=256 -> 81920
#define WK2_OFF   118784            // kW[0]:   Kp=128, M=256 -> 32768
#define WK3_OFF   151552            // kW[1]:   Kp=128, M=256 -> 32768
#define WE1_OFF   184320            // c1eW padded [16,64]->[16,128]: 8x128 = 1024
#define WEC_OFF   185344            // ceW[i] [16,128]: 8x128 each (x4) = 4096
#define WTOT      189440
__device__ unsigned g_Bh[WTOT];
__device__ unsigned g_Bl[WTOT];

__device__ __forceinline__ float dleaky(float v) {
    float t = v > 0.f ? v : 0.01f * v;
    return t > 0.f ? t : 0.01f * t;
}
__device__ __forceinline__ float leaky1(float v) {
    return v > 0.f ? v : 0.01f * v;
}

__device__ __forceinline__ unsigned pack_bf16(float lo, float hi) {
    __nv_bfloat162 h = __floats2bfloat162_rn(lo, hi);
    return *(unsigned*)&h;
}

// ---------------------------------------------------------------------------
// Fused: blocks [0, CNT_BLK) count edge dst; rest convert weights to bf16 hi/lo
// ---------------------------------------------------------------------------
#define CNT_BLK 3125                 // ceil(EE/256)
#define WCVT_BLK 740                 // ceil(WTOT/256)

__global__ void wcvt_count_kernel(const int* __restrict__ dstv,
                                  const float* __restrict__ c1W,
                                  const float* __restrict__ cW,
                                  const float* __restrict__ k1W,
                                  const float* __restrict__ kW,
                                  const float* __restrict__ c1eW,
                                  const float* __restrict__ ceW) {
    if (blockIdx.x < CNT_BLK) {
        int e = blockIdx.x * blockDim.x + threadIdx.x;
        if (e < EE) atomicAdd(&g_cnt[dstv[e]], 1);
        return;
    }
    int widx = (blockIdx.x - CNT_BLK) * blockDim.x + threadIdx.x;
    if (widx >= WTOT) return;
    float v0, v1;
    if (widx < WCV_OFF) {                         // conv1W [64,128]
        int kp = widx >> 7, m = widx & 127;
        v0 = c1W[(size_t)(2 * kp) * 128 + m];
        v1 = c1W[(size_t)(2 * kp + 1) * 128 + m];
    } else if (widx < WK1_OFF) {                  // convW[i] [128,128]
        int r = widx - WCV_OFF;
        int i = r >> 13; r &= 8191;
        const float* s = cW + (size_t)i * OUTD * OUTD;
        int kp = r >> 7, m = r & 127;
        v0 = s[(size_t)(2 * kp) * 128 + m];
        v1 = s[(size_t)(2 * kp + 1) * 128 + m];
    } else if (widx < WK2_OFF) {                  // cls1W [640,256]
        int r = widx - WK1_OFF;
        int kp = r >> 8, m = r & 255;
        v0 = k1W[(size_t)(2 * kp) * 256 + m];
        v1 = k1W[(size_t)(2 * kp + 1) * 256 + m];
    } else if (widx < WK3_OFF) {                  // kW[0] [256,256]
        int r = widx - WK2_OFF;
        int kp = r >> 8, m = r & 255;
        v0 = kW[(size_t)(2 * kp) * 256 + m];
        v1 = kW[(size_t)(2 * kp + 1) * 256 + m];
    } else if (widx < WE1_OFF) {                  // kW[1] [256,256]
        int r = widx - WK3_OFF;
        const float* s = kW + CLSD * CLSD;
        int kp = r >> 8, m = r & 255;
        v0 = s[(size_t)(2 * kp) * 256 + m];
        v1 = s[(size_t)(2 * kp + 1) * 256 + m];
    } else if (widx < WEC_OFF) {                  // c1eW [16,64] padded to 128
        int r = widx - WE1_OFF;
        int kp = r >> 7, m = r & 127;
        v0 = (m < 64) ? c1eW[(size_t)(2 * kp) * 64 + m] : 0.f;
        v1 = (m < 64) ? c1eW[(size_t)(2 * kp + 1) * 64 + m] : 0.f;
    } else {                                      // ceW[i] [16,128]
        int r = widx - WEC_OFF;
        int i = r >> 10; r &= 1023;
        const float* s = ceW + (size_t)i * EDD * OUTD;
        int kp = r >> 7, m = r & 127;
        v0 = s[(size_t)(2 * kp) * 128 + m];
        v1 = s[(size_t)(2 * kp + 1) * 128 + m];
    }
    float h0 = __bfloat162float(__float2bfloat16(v0));
    float h1 = __bfloat162float(__float2bfloat16(v1));
    g_Bh[widx] = pack_bf16(h0, h1);
    g_Bl[widx] = pack_bf16(v0 - h0, v1 - h1);
}

// ---------------------------------------------------------------------------
// Scan: g_cnt -> g_off/g_cur, then zero g_cnt
// ---------------------------------------------------------------------------
__global__ void csr_scan_kernel() {
    __shared__ int part[1024];
    const int CH = (NN + 1023) / 1024;
    int t = threadIdx.x;
    int start = t * CH;
    int sum = 0;
    for (int i = 0; i < CH; i++) {
        int idx = start + i;
        if (idx < NN) sum += g_cnt[idx];
    }
    part[t] = sum;
    __syncthreads();
    for (int o = 1; o < 1024; o <<= 1) {
        int v = (t >= o) ? part[t - o] : 0;
        __syncthreads();
        part[t] += v;
        __syncthreads();
    }
    int run = part[t] - sum;
    for (int i = 0; i < CH; i++) {
        int idx = start + i;
        if (idx < NN) {
            g_off[idx] = run;
            g_cur[idx] = run;
            run += g_cnt[idx];
            g_cnt[idx] = 0;
        }
    }
    if (t == 0) g_off[NN] = EE;
}

// ---------------------------------------------------------------------------
// Fill + permute fused: 4 threads per edge.
// ---------------------------------------------------------------------------
__global__ void fill_permute_kernel(const int* __restrict__ srcv,
                                    const int* __restrict__ dstv,
                                    const float* __restrict__ attr) {
    int idx = blockIdx.x * blockDim.x + threadIdx.x;   // EE*4
    if (idx >= EE * 4) return;
    int e = idx >> 2, c4 = idx & 3;
    int lane = threadIdx.x & 31;
    int pos = 0;
    if (c4 == 0) pos = atomicAdd(&g_cur[dstv[e]], 1);
    pos = __shfl_sync(0xffffffffu, pos, lane & ~3);
    float4 v = __ldg((const float4*)&attr[(size_t)e * 16 + c4 * 4]);
    *(float4*)&g_attrs[(size_t)pos * 16 + c4 * 4] = v;
    if (c4 == 0) g_srcs[pos] = __ldg(&srcv[e]);
}

// ---------------------------------------------------------------------------
// Edge-MLP GEMM: E[e][c] = attrs[e][0:16] @ eW[16][c] + eb[c]  -> fp16
// Tile 128 edges x 128 cols, K=16 (single iteration). bf16 hi/lo split.
// B pre-converted (padded to 128 cols for conv1); write only c < Dout, ldc=Dout.
// ---------------------------------------------------------------------------
__device__ __forceinline__ void mma_bf16(float* acc, const unsigned* a, const unsigned* b) {
    asm volatile(
        "mma.sync.aligned.m16n8k16.row.col.f32.bf16.bf16.f32 "
        "{%0,%1,%2,%3}, {%4,%5,%6,%7}, {%8,%9}, {%0,%1,%2,%3};"
        : "+f"(acc[0]), "+f"(acc[1]), "+f"(acc[2]), "+f"(acc[3])
        : "r"(a[0]), "r"(a[1]), "r"(a[2]), "r"(a[3]), "r"(b[0]), "r"(b[1]));
}

__global__ __launch_bounds__(256)
void egemm_kernel(const float* __restrict__ A,          // [Nrows,16] CSR attrs
                  const unsigned* __restrict__ PBh,
                  const unsigned* __restrict__ PBl,
                  const float* __restrict__ bias,
                  __half* __restrict__ Eout,
                  int Nrows, int Dout) {
    __shared__ unsigned sAh[128][9];
    __shared__ unsigned sAl[128][9];
    __shared__ unsigned sBh[128][9];
    __shared__ unsigned sBl[128][9];

    const int tid = threadIdx.x;
    const int lane = tid & 31;
    const int wid = tid >> 5;
    const int wm = (wid & 1) * 64;
    const int wn = (wid >> 1) * 32;
    const int row0 = blockIdx.y * 128;

    float acc[16][4];
#pragma unroll
    for (int i = 0; i < 16; i++)
#pragma unroll
        for (int j = 0; j < 4; j++) acc[i][j] = 0.f;

#pragma unroll
    for (int j = 0; j < 2; j++) {
        int idx = j * 256 + tid;
        int m = idx >> 2, kk = (idx & 3) << 2;
        int r = row0 + m;
        float4 v = make_float4(0.f, 0.f, 0.f, 0.f);
        if (r < Nrows) v = *(const float4*)&A[(size_t)r * 16 + kk];
        int kp = (idx & 3) << 1;
        float hx = __bfloat162float(__float2bfloat16(v.x));
        float hy = __bfloat162float(__float2bfloat16(v.y));
        float hz = __bfloat162float(__float2bfloat16(v.z));
        float hw = __bfloat162float(__float2bfloat16(v.w));
        sAh[m][kp]     = pack_bf16(hx, hy);
        sAh[m][kp + 1] = pack_bf16(hz, hw);
        sAl[m][kp]     = pack_bf16(v.x - hx, v.y - hy);
        sAl[m][kp + 1] = pack_bf16(v.z - hz, v.w - hw);

        int n = (idx & 63) << 1, bkp = idx >> 6;
        uint2 gh = *(const uint2*)&PBh[(size_t)bkp * 128 + n];
        uint2 gl = *(const uint2*)&PBl[(size_t)bkp * 128 + n];
        sBh[n][bkp]     = gh.x;
        sBh[n + 1][bkp] = gh.y;
        sBl[n][bkp]     = gl.x;
        sBl[n + 1][bkp] = gl.y;
    }
    __syncthreads();

    unsigned af[4][4], bh[4][2], bl[4][2];
    const int ar = lane >> 2, ak = lane & 3;
#pragma unroll
    for (int i = 0; i < 4; i++) {
        int m = wm + i * 16 + ar;
        af[i][0] = sAh[m][ak];
        af[i][1] = sAh[m + 8][ak];
        af[i][2] = sAh[m][ak + 4];
        af[i][3] = sAh[m + 8][ak + 4];
    }
#pragma unroll
    for (int j = 0; j < 4; j++) {
        int nn = wn + j * 8 + (lane >> 2);
        bh[j][0] = sBh[nn][lane & 3];
        bh[j][1] = sBh[nn][(lane & 3) + 4];
        bl[j][0] = sBl[nn][lane & 3];
        bl[j][1] = sBl[nn][(lane & 3) + 4];
    }
#pragma unroll
    for (int i = 0; i < 4; i++)
#pragma unroll
        for (int j = 0; j < 4; j++) mma_bf16(acc[i * 4 + j], af[i], bh[j]);
#pragma unroll
    for (int i = 0; i < 4; i++)
#pragma unroll
        for (int j = 0; j < 4; j++) mma_bf16(acc[i * 4 + j], af[i], bl[j]);
#pragma unroll
    for (int i = 0; i < 4; i++) {
        int m = wm + i * 16 + ar;
        af[i][0] = sAl[m][ak];
        af[i][1] = sAl[m + 8][ak];
        af[i][2] = sAl[m][ak + 4];
        af[i][3] = sAl[m + 8][ak + 4];
    }
#pragma unroll
    for (int i = 0; i < 4; i++)
#pragma unroll
        for (int j = 0; j < 4; j++) mma_bf16(acc[i * 4 + j], af[i], bh[j]);

    // epilogue: bias + fp16 store (only cols < Dout)
#pragma unroll
    for (int i = 0; i < 4; i++) {
#pragma unroll
        for (int j = 0; j < 4; j++) {
            int r = row0 + wm + i * 16 + (lane >> 2);
            int c = wn + j * 8 + (lane & 3) * 2;
            if (c >= Dout) continue;
            float* ap = acc[i * 4 + j];
#pragma unroll
            for (int h = 0; h < 2; h++) {
                int rr = r + h * 8;
                if (rr >= Nrows) continue;
                float v0 = ap[h * 2 + 0] + bias[c];
                float v1 = ap[h * 2 + 1] + bias[c + 1];
                *(__half2*)&Eout[(size_t)rr * Dout + c] = __floats2half2_rn(v0, v1);
            }
        }
    }
}

// ---------------------------------------------------------------------------
// Gather (no MLP): cp.async smem ring, 2-edge commit groups (R12 pipeline).
// WPN warps per node; each warp owns a fixed 64-column half (2 floats/lane).
//   agg[n] = x[n] + sum_{e: dst=n} relu(x[src[e]] + E[e])
// E precomputed in fp16 by egemm.
// ---------------------------------------------------------------------------
template <int WPN>
__global__ __launch_bounds__(128, 12)
void gather_kernel(const float* __restrict__ x, int ldx,
                   const __half* __restrict__ emat,
                   float* __restrict__ agg) {
    constexpr int D = WPN * 64;        // agg/E row width
    constexpr int XB = 256;            // x-half bytes per warp
    constexpr int SLOT = XB + 128;     // + e-half (64 halves = 128B)
    constexpr int NS = 8;              // ring slots
    constexpr int LAG = 3;             // lookahead groups (2 edges each)

    __shared__ __align__(16) char s_ring[4 * NS * SLOT];   // 12 KB

    const int tid = threadIdx.x;
    const int lane = tid & 31;
    const int wIn = tid >> 5;
    char* ring = s_ring + wIn * (NS * SLOT);

    const int gw = (blockIdx.x * blockDim.x + tid) >> 5;
    const int n = gw / WPN;
    const int half = gw - n * WPN;
    if (n >= NN) return;
    const int col = half * 64 + lane * 2;

    const int i0 = __ldg(&g_off[n]);
    const int i1 = __ldg(&g_off[n + 1]);

    float acc0, acc1;
    {
        float2 xv = *(const float2*)&x[(size_t)n * ldx + col];
        acc0 = xv.x; acc1 = xv.y;
    }

    const int T = i1 - i0;
    const int G = (T + 1) >> 1;

    auto issue_edge = [&](int pos, int s) {
        if (pos < i1) {
            char* sp = ring + (pos & (NS - 1)) * SLOT;
            const float* grow = x + (size_t)s * ldx + col;
            unsigned sx = (unsigned)__cvta_generic_to_shared(sp) + lane * 8;
            asm volatile("cp.async.ca.shared.global [%0], [%1], 8;"
                         :: "r"(sx), "l"(grow));
            const __half* ge = emat + (size_t)pos * D + col;
            unsigned se = (unsigned)__cvta_generic_to_shared(sp) + XB + lane * 4;
            asm volatile("cp.async.ca.shared.global [%0], [%1], 4;"
                         :: "r"(se), "l"(ge));
        }
    };

    auto ld_srcs2 = [&](int g, int& a, int& b) {
        int p = i0 + 2 * g;
        a = (p < i1) ? __ldg(&g_srcs[p]) : 0;
        b = (p + 1 < i1) ? __ldg(&g_srcs[p + 1]) : 0;
    };

    auto process = [&](int pos) {
        const char* sp = ring + (pos & (NS - 1)) * SLOT;
        float2 xr = *(const float2*)(sp + lane * 8);
        __half2 eh = *(const __half2*)(sp + XB + lane * 4);
        float2 ef = __half22float2(eh);
        float m0 = xr.x + ef.x;
        float m1 = xr.y + ef.y;
        acc0 += m0 > 0.f ? m0 : 0.f;
        acc1 += m1 > 0.f ? m1 : 0.f;
    };

    int sA, sB;
#pragma unroll
    for (int j = 0; j < LAG; j++) {
        ld_srcs2(j, sA, sB);
        issue_edge(i0 + 2 * j, sA);
        issue_edge(i0 + 2 * j + 1, sB);
        asm volatile("cp.async.commit_group;" ::: "memory");
    }
    ld_srcs2(LAG, sA, sB);

    for (int g = 0; g < G; g++) {
        int nA, nB;
        ld_srcs2(g + LAG + 1, nA, nB);
        int p = i0 + 2 * (g + LAG);
        issue_edge(p, sA);
        issue_edge(p + 1, sB);
        asm volatile("cp.async.commit_group;" ::: "memory");
        sA = nA; sB = nB;

        asm volatile("cp.async.wait_group 3;" ::: "memory");
        __syncwarp();

        int q = i0 + 2 * g;
        process(q);
        if (q + 1 < i1) process(q + 1);
    }

    *(float2*)&g_agg[(size_t)n * D + col] = make_float2(acc0, acc1);
}

// ---------------------------------------------------------------------------
// Split-bf16 tensor-core GEMM with pre-converted packed B (node/classifier).
// ---------------------------------------------------------------------------
template <int ACT>
__global__ __launch_bounds__(256)
void bf16_gemm(const float* __restrict__ A, int lda,
               const unsigned* __restrict__ PBh,
               const unsigned* __restrict__ PBl,
               const float* __restrict__ bias,
               const float* __restrict__ gamma,
               const float* __restrict__ beta,
               float* __restrict__ Cmat, int ldc,
               int Nrows, int K, int M, float bn_inv) {
    __shared__ unsigned sAh[128][9];
    __shared__ unsigned sAl[128][9];
    __shared__ unsigned sBh[128][9];
    __shared__ unsigned sBl[128][9];

    const int tid = threadIdx.x;
    const int lane = tid & 31;
    const int wid = tid >> 5;
    const int wm = (wid & 1) * 64;
    const int wn = (wid >> 1) * 32;
    const int row0 = blockIdx.y * 128;
    const int col0 = blockIdx.x * 128;

    float acc[16][4];
#pragma unroll
    for (int i = 0; i < 16; i++)
#pragma unroll
        for (int j = 0; j < 4; j++) acc[i][j] = 0.f;

    float4 ga[2];
    uint2 gh[2], gl[2];

    auto load_tile = [&](int k0) {
#pragma unroll
        for (int j = 0; j < 2; j++) {
            int idx = j * 256 + tid;
            int m = idx >> 2, kk = (idx & 3) << 2;
            int r = row0 + m;
            ga[j] = make_float4(0.f, 0.f, 0.f, 0.f);
            if (r < Nrows) ga[j] = *(const float4*)&A[(size_t)r * lda + k0 + kk];
            int n = (idx & 63) << 1, bkp = idx >> 6;
            size_t off = (size_t)(k0 / 2 + bkp) * M + col0 + n;
            gh[j] = *(const uint2*)&PBh[off];
            gl[j] = *(const uint2*)&PBl[off];
        }
    };

    load_tile(0);

    for (int k0 = 0; k0 < K; k0 += 16) {
        __syncthreads();
#pragma unroll
        for (int j = 0; j < 2; j++) {
            int idx = j * 256 + tid;
            int m = idx >> 2, kp = (idx & 3) << 1;
            float4 v = ga[j];
            float hx = __bfloat162float(__float2bfloat16(v.x));
            float hy = __bfloat162float(__float2bfloat16(v.y));
            float hz = __bfloat162float(__float2bfloat16(v.z));
            float hw = __bfloat162float(__float2bfloat16(v.w));
            sAh[m][kp]     = pack_bf16(hx, hy);
            sAh[m][kp + 1] = pack_bf16(hz, hw);
            sAl[m][kp]     = pack_bf16(v.x - hx, v.y - hy);
            sAl[m][kp + 1] = pack_bf16(v.z - hz, v.w - hw);

            int n = (idx & 63) << 1, bkp = idx >> 6;
            sBh[n][bkp]     = gh[j].x;
            sBh[n + 1][bkp] = gh[j].y;
            sBl[n][bkp]     = gl[j].x;
            sBl[n + 1][bkp] = gl[j].y;
        }
        __syncthreads();

        if (k0 + 16 < K) load_tile(k0 + 16);

        unsigned af[4][4], bh[4][2], bl[4][2];
        const int ar = lane >> 2, ak = lane & 3;
#pragma unroll
        for (int i = 0; i < 4; i++) {
            int m = wm + i * 16 + ar;
            af[i][0] = sAh[m][ak];
            af[i][1] = sAh[m + 8][ak];
            af[i][2] = sAh[m][ak + 4];
            af[i][3] = sAh[m + 8][ak + 4];
        }
#pragma unroll
        for (int j = 0; j < 4; j++) {
            int nn = wn + j * 8 + (lane >> 2);
            bh[j][0] = sBh[nn][lane & 3];
            bh[j][1] = sBh[nn][(lane & 3) + 4];
            bl[j][0] = sBl[nn][lane & 3];
            bl[j][1] = sBl[nn][(lane & 3) + 4];
        }
#pragma unroll
        for (int i = 0; i < 4; i++)
#pragma unroll
            for (int j = 0; j < 4; j++) mma_bf16(acc[i * 4 + j], af[i], bh[j]);
#pragma unroll
        for (int i = 0; i < 4; i++)
#pragma unroll
            for (int j = 0; j < 4; j++) mma_bf16(acc[i * 4 + j], af[i], bl[j]);
#pragma unroll
        for (int i = 0; i < 4; i++) {
            int m = wm + i * 16 + ar;
            af[i][0] = sAl[m][ak];
            af[i][1] = sAl[m + 8][ak];
            af[i][2] = sAl[m][ak + 4];
            af[i][3] = sAl[m + 8][ak + 4];
        }
#pragma unroll
        for (int i = 0; i < 4; i++)
#pragma unroll
            for (int j = 0; j < 4; j++) mma_bf16(acc[i * 4 + j], af[i], bh[j]);
    }

    // epilogue
#pragma unroll
    for (int i = 0; i < 4; i++) {
#pragma unroll
        for (int j = 0; j < 4; j++) {
            int r = row0 + wm + i * 16 + (lane >> 2);
            int c = col0 + wn + j * 8 + (lane & 3) * 2;
            float* ap = acc[i * 4 + j];
#pragma unroll
            for (int h = 0; h < 2; h++) {
                int rr = r + h * 8;
                if (rr >= Nrows) continue;
                float v0 = ap[h * 2 + 0] + bias[c];
                float v1 = ap[h * 2 + 1] + bias[c + 1];
                if (gamma != nullptr) {
                    v0 = gamma[c] * (v0 * bn_inv) + beta[c];
                    v1 = gamma[c + 1] * (v1 * bn_inv) + beta[c + 1];
                }
                if (ACT == 1) { v0 = leaky1(v0); v1 = leaky1(v1); }
                else if (ACT == 2) { v0 = dleaky(v0); v1 = dleaky(v1); }
                *(float2*)&Cmat[(size_t)rr * ldc + c] = make_float2(v0, v1);
            }
        }
    }
}

// ---------------------------------------------------------------------------
// Pooling
// ---------------------------------------------------------------------------
__global__ void zero_pool_kernel() {
    int idx = blockIdx.x * blockDim.x + threadIdx.x;
    if (idx < NMOL * 128 / 4)
        *(float4*)&g_pool[idx * 4] = make_float4(0.f, 0.f, 0.f, 0.f);
}

__global__ void pool_kernel(const int* __restrict__ batch) {
    int idx = blockIdx.x * blockDim.x + threadIdx.x;
    int n = idx >> 5;
    if (n >= NN) return;
    int c4 = (idx & 31) << 2;
    float4 v = *(const float4*)&g_HS[(size_t)n * HSW + 384 + c4];
    float* p = g_pool + (size_t)batch[n] * 128 + c4;
    asm volatile("red.global.add.v4.f32 [%0], {%1,%2,%3,%4};"
                 :: "l"(p), "f"(v.x), "f"(v.y), "f"(v.z), "f"(v.w) : "memory");
}

__global__ void bcast_kernel(const int* __restrict__ batch) {
    int idx = blockIdx.x * blockDim.x + threadIdx.x;
    int n = idx >> 5;
    if (n >= NN) return;
    int c4 = (idx & 31) << 2;
    float4 v = *(const float4*)&g_pool[(size_t)batch[n] * 128 + c4];
    *(float4*)&g_HS[(size_t)n * HSW + 512 + c4] = v;
}

// ---------------------------------------------------------------------------
// Final: out[n] = sigmoid(Z1[n,:] . fW + fb)
// ---------------------------------------------------------------------------
__global__ void final_kernel(const float* __restrict__ Z,
                             const float* __restrict__ fW,
                             const float* __restrict__ fb,
                             float* __restrict__ out) {
    int idx = blockIdx.x * blockDim.x + threadIdx.x;
    int n = idx >> 5;
    if (n >= NN) return;
    int lane = idx & 31;
    float s = 0.f;
#pragma unroll
    for (int j = lane; j < CLSD; j += 32)
        s = fmaf(Z[(size_t)n * CLSD + j], fW[j], s);
#pragma unroll
    for (int o = 16; o; o >>= 1) s += __shfl_xor_sync(0xffffffffu, s, o);
    if (lane == 0) {
        float z = s + fb[0];
        out[n] = 1.f / (1.f + expf(-z));
    }
}

// ---------------------------------------------------------------------------
// Launch
// ---------------------------------------------------------------------------
extern "C" void kernel_launch(void* const* d_in, const int* in_sizes, int n_in,
                              void* d_out, int out_size) {
    const float* x    = (const float*)d_in[0];
    const int*   ei   = (const int*)d_in[1];
    const float* attr = (const float*)d_in[2];
    const int*   batch= (const int*)d_in[3];
    const float* c1W  = (const float*)d_in[4];
    const float* c1b  = (const float*)d_in[5];
    const float* c1g  = (const float*)d_in[6];
    const float* c1be = (const float*)d_in[7];
    const float* c1eW = (const float*)d_in[8];
    const float* c1eb = (const float*)d_in[9];
    const float* cW   = (const float*)d_in[10];
    const float* cb   = (const float*)d_in[11];
    const float* cg   = (const float*)d_in[12];
    const float* cbe  = (const float*)d_in[13];
    const float* ceW  = (const float*)d_in[14];
    const float* ceb  = (const float*)d_in[15];
    const float* k1W  = (const float*)d_in[16];
    const float* k1b  = (const float*)d_in[17];
    const float* kW   = (const float*)d_in[18];
    const float* kb   = (const float*)d_in[19];
    const float* fW   = (const float*)d_in[20];
    const float* fb   = (const float*)d_in[21];
    float* out = (float*)d_out;

    const int* srcp = ei;
    const int* dstp = ei + EE;

    const float bn_inv = (float)(1.0 / (double)((float)sqrt(1.0 + 1e-5)));

    float *agg, *h0, *HS, *z1, *attrs;
    unsigned *Bh, *Bl;
    __half* emat;
    float* z2;
    cudaGetSymbolAddress((void**)&agg, g_agg);
    cudaGetSymbolAddress((void**)&h0,  g_h0);
    cudaGetSymbolAddress((void**)&HS,  g_HS);
    cudaGetSymbolAddress((void**)&z1,  g_z1);
    cudaGetSymbolAddress((void**)&z2,  g_z2);
    cudaGetSymbolAddress((void**)&Bh,  g_Bh);
    cudaGetSymbolAddress((void**)&Bl,  g_Bl);
    cudaGetSymbolAddress((void**)&attrs, g_attrs);
    cudaGetSymbolAddress((void**)&emat, g_emat);

    // ---- CSR build + weight conversion ----
    wcvt_count_kernel<<<CNT_BLK + WCVT_BLK, 256>>>(dstp, c1W, cW, k1W, kW, c1eW, ceW);
    csr_scan_kernel<<<1, 1024>>>();
    fill_permute_kernel<<<(EE * 4 + 255) / 256, 256>>>(srcp, dstp, attr);

    const dim3 egrid(1, (EE + 127) / 128);

    // ---- conv1 (64 -> 128): edge-MLP GEMM then gather, 1 warp per node ----
    {
        egemm_kernel<<<egrid, 256>>>(attrs, Bh + WE1_OFF, Bl + WE1_OFF,
                                     c1eb, emat, EE, 64);
        gather_kernel<1><<<(NN + 3) / 4, 128>>>(x, INRR, emat, agg);
        dim3 grid(1, (NN + 127) / 128);
        bf16_gemm<2><<<grid, 256>>>(agg, 64, Bh + WC1_OFF, Bl + WC1_OFF,
                                    c1b, c1g, c1be, h0, 128, NN, 64, 128, bn_inv);
    }

    // ---- conv loop (4 layers, 128 -> 128): 2 warps per node ----
    for (int i = 0; i < 4; i++) {
        const float* inPtr = (i == 0) ? h0 : (HS + (size_t)(i - 1) * 128);
        int ldin = (i == 0) ? 128 : HSW;
        egemm_kernel<<<egrid, 256>>>(attrs,
                                     Bh + WEC_OFF + (size_t)i * 1024,
                                     Bl + WEC_OFF + (size_t)i * 1024,
                                     ceb + (size_t)i * OUTD, emat, EE, 128);
        gather_kernel<2><<<(NN * 2 + 3) / 4, 128>>>(inPtr, ldin, emat, agg);
        dim3 grid(1, (NN + 127) / 128);
        bf16_gemm<2><<<grid, 256>>>(agg, 128,
                                    Bh + WCV_OFF + (size_t)i * 8192,
                                    Bl + WCV_OFF + (size_t)i * 8192,
                                    cb + (size_t)i * OUTD,
                                    cg + (size_t)i * OUTD,
                                    cbe + (size_t)i * OUTD,
                                    HS + (size_t)i * 128, HSW,
                                    NN, 128, 128, bn_inv);
    }

    // ---- global_add_pool + broadcast ----
    zero_pool_kernel<<<(NMOL * 128 / 4 + 255) / 256, 256>>>();
    pool_kernel<<<(NN * 32 + 255) / 256, 256>>>(batch);
    bcast_kernel<<<(NN * 32 + 255) / 256, 256>>>(batch);

    // ---- classifier ----
    {
        dim3 grid1(CLSD / 128, (NN + 127) / 128);
        bf16_gemm<0><<<grid1, 256>>>(HS, HSW, Bh + WK1_OFF, Bl + WK1_OFF,
                                     k1b, nullptr, nullptr,
                                     z1, CLSD, NN, HSW, CLSD, bn_inv);
        bf16_gemm<1><<<grid1, 256>>>(z1, CLSD, Bh + WK2_OFF, Bl + WK2_OFF,
                                     kb, nullptr, nullptr,
                                     z2, CLSD, NN, CLSD, CLSD, bn_inv);
        bf16_gemm<1><<<grid1, 256>>>(z2, CLSD, Bh + WK3_OFF, Bl + WK3_OFF,
                                     kb + CLSD, nullptr, nullptr,
                                     z1, CLSD, NN, CLSD, CLSD, bn_inv);
    }

    // ---- final dot + sigmoid ----
    final_kernel<<<(NN * 32 + 255) / 256, 256>>>(z1, fW, fb, out);
}

// round 17
// speedup vs baseline: 1.1137x; 1.1137x over previous
#include <cuda_runtime.h>
#include <cuda_bf16.h>
#include <cuda_fp16.h>
#include <math.h>

// Problem constants
#define NN   50000
#define EE   800000
#define NMOL 2000
#define INRR 64
#define OUTD 128
#define EDD  16
#define CLSD 256
#define HSW  640   // OUT*(L_CONV+1)

// Static scratch (no allocations allowed)
__device__ float g_agg[(size_t)NN * 128];
__device__ float g_h0[(size_t)NN * 128];
__device__ float g_HS[(size_t)NN * HSW];
__device__ float g_pool[(size_t)NMOL * 128];
__device__ float g_z1[(size_t)NN * CLSD];
__device__ float g_z2[(size_t)NN * CLSD];
__device__ __half g_xh[(size_t)NN * 128];        // fp16 mirror of node features
// CSR (by dst) — g_cnt zero at load; csr_scan re-zeroes it each call.
__device__ int g_cnt[NN];
__device__ int g_off[NN + 1];
__device__ int g_cur[NN];
__device__ int g_srcs[EE];                       // CSR-ordered src node
__device__ float g_attrs[(size_t)EE * 16];       // CSR-ordered edge_attr

// Pre-converted packed bf16 weights (hi/lo split).
#define WC1_OFF   0                 // conv1W:  Kp=32,  M=128 -> 4096
#define WCV_OFF   4096              // convW i: Kp=64,  M=128 -> 8192 each (x4)
#define WK1_OFF   36864             // cls1W:   Kp=320, M=256 -> 81920
#define WK2_OFF   118784            // kW[0]:   Kp=128, M=256 -> 32768
#define WK3_OFF   151552            // kW[1]:   Kp=128, M=256 -> 32768
#define WTOT      184320
__device__ unsigned g_Bh[WTOT];
__device__ unsigned g_Bl[WTOT];

__device__ __forceinline__ float dleaky(float v) {
    float t = v > 0.f ? v : 0.01f * v;
    return t > 0.f ? t : 0.01f * t;
}
__device__ __forceinline__ float leaky1(float v) {
    return v > 0.f ? v : 0.01f * v;
}

// f32x2 helpers
__device__ __forceinline__ unsigned long long packf2(float lo, float hi) {
    unsigned long long r;
    asm("mov.b64 %0, {%1, %2};" : "=l"(r) : "r"(__float_as_uint(lo)), "r"(__float_as_uint(hi)));
    return r;
}
__device__ __forceinline__ unsigned long long dupf2(float v) {
    unsigned long long r;
    unsigned b = __float_as_uint(v);
    asm("mov.b64 %0, {%1, %1};" : "=l"(r) : "r"(b));
    return r;
}
__device__ __forceinline__ void fma2(unsigned long long& d,
                                     unsigned long long a, unsigned long long b) {
    asm("fma.rn.f32x2 %0, %1, %2, %0;" : "+l"(d) : "l"(a), "l"(b));
}
__device__ __forceinline__ void unpackf2(unsigned long long v, float& lo, float& hi) {
    unsigned ulo, uhi;
    asm("mov.b64 {%0, %1}, %2;" : "=r"(ulo), "=r"(uhi) : "l"(v));
    lo = __uint_as_float(ulo);
    hi = __uint_as_float(uhi);
}

__device__ __forceinline__ unsigned pack_bf16(float lo, float hi) {
    __nv_bfloat162 h = __floats2bfloat162_rn(lo, hi);
    return *(unsigned*)&h;
}

// ---------------------------------------------------------------------------
// Fused: blocks [0, CNT_BLK) count edge dst; rest convert weights to bf16 hi/lo
// ---------------------------------------------------------------------------
#define CNT_BLK 3125                 // ceil(EE/256)
#define WCVT_BLK 720                 // ceil(WTOT/256)

__global__ void wcvt_count_kernel(const int* __restrict__ dstv,
                                  const float* __restrict__ c1W,
                                  const float* __restrict__ cW,
                                  const float* __restrict__ k1W,
                                  const float* __restrict__ kW) {
    if (blockIdx.x < CNT_BLK) {
        int e = blockIdx.x * blockDim.x + threadIdx.x;
        if (e < EE) atomicAdd(&g_cnt[dstv[e]], 1);
        return;
    }
    int widx = (blockIdx.x - CNT_BLK) * blockDim.x + threadIdx.x;
    if (widx >= WTOT) return;
    const float* src;
    int M, kp, m;
    if (widx < WCV_OFF) {
        src = c1W; M = 128;
        kp = widx >> 7; m = widx & 127;
    } else if (widx < WK1_OFF) {
        int r = widx - WCV_OFF;
        int i = r >> 13; r &= 8191;
        src = cW + (size_t)i * OUTD * OUTD; M = 128;
        kp = r >> 7; m = r & 127;
    } else if (widx < WK2_OFF) {
        int r = widx - WK1_OFF;
        src = k1W; M = 256;
        kp = r >> 8; m = r & 255;
    } else if (widx < WK3_OFF) {
        int r = widx - WK2_OFF;
        src = kW; M = 256;
        kp = r >> 8; m = r & 255;
    } else {
        int r = widx - WK3_OFF;
        src = kW + CLSD * CLSD; M = 256;
        kp = r >> 8; m = r & 255;
    }
    float v0 = src[(size_t)(2 * kp) * M + m];
    float v1 = src[(size_t)(2 * kp + 1) * M + m];
    float h0 = __bfloat162float(__float2bfloat16(v0));
    float h1 = __bfloat162float(__float2bfloat16(v1));
    g_Bh[widx] = pack_bf16(h0, h1);
    g_Bl[widx] = pack_bf16(v0 - h0, v1 - h1);
}

// ---------------------------------------------------------------------------
// Scan: g_cnt -> g_off/g_cur, then zero g_cnt
// ---------------------------------------------------------------------------
__global__ void csr_scan_kernel() {
    __shared__ int part[1024];
    const int CH = (NN + 1023) / 1024;
    int t = threadIdx.x;
    int start = t * CH;
    int sum = 0;
    for (int i = 0; i < CH; i++) {
        int idx = start + i;
        if (idx < NN) sum += g_cnt[idx];
    }
    part[t] = sum;
    __syncthreads();
    for (int o = 1; o < 1024; o <<= 1) {
        int v = (t >= o) ? part[t - o] : 0;
        __syncthreads();
        part[t] += v;
        __syncthreads();
    }
    int run = part[t] - sum;
    for (int i = 0; i < CH; i++) {
        int idx = start + i;
        if (idx < NN) {
            g_off[idx] = run;
            g_cur[idx] = run;
            run += g_cnt[idx];
            g_cnt[idx] = 0;
        }
    }
    if (t == 0) g_off[NN] = EE;
}

// ---------------------------------------------------------------------------
// Fill + permute fused: 4 threads per edge.
// ---------------------------------------------------------------------------
__global__ void fill_permute_kernel(const int* __restrict__ srcv,
                                    const int* __restrict__ dstv,
                                    const float* __restrict__ attr) {
    int idx = blockIdx.x * blockDim.x + threadIdx.x;   // EE*4
    if (idx >= EE * 4) return;
    int e = idx >> 2, c4 = idx & 3;
    int lane = threadIdx.x & 31;
    int pos = 0;
    if (c4 == 0) pos = atomicAdd(&g_cur[dstv[e]], 1);
    pos = __shfl_sync(0xffffffffu, pos, lane & ~3);
    float4 v = __ldg((const float4*)&attr[(size_t)e * 16 + c4 * 4]);
    *(float4*)&g_attrs[(size_t)pos * 16 + c4 * 4] = v;
    if (c4 == 0) g_srcs[pos] = __ldg(&srcv[e]);
}

// ---------------------------------------------------------------------------
// Input x -> fp16 mirror (ld 64) for conv1's gather.
// ---------------------------------------------------------------------------
__global__ void x2h_kernel(const float* __restrict__ x) {
    int idx = blockIdx.x * blockDim.x + threadIdx.x;   // NN*32
    if (idx >= NN * 32) return;
    float2 v = *(const float2*)&x[(size_t)idx * 2];
    *(__half2*)&g_xh[(size_t)idx * 2] = __floats2half2_rn(v.x, v.y);
}

// ---------------------------------------------------------------------------
// Gather with cp.async smem ring, 2-edge commit groups (R12 pipeline),
// neighbor x rows read from fp16 mirror (half the bytes); self term fp32.
// WPN warps per node; each warp owns a fixed 64-column half (2 cols/lane),
// edge-MLP weights (16 f32x2 words) in REGISTERS.
//   agg[n] = x[n] + sum_{e: dst=n} relu(x[src[e]] + attr[e]@eW + eb)
// ---------------------------------------------------------------------------
template <int WPN>
__global__ __launch_bounds__(128, 8)
void gather_kernel(const __half* __restrict__ xh, int ldh,
                   const float* __restrict__ xf, int ldf,
                   const float* __restrict__ eW,
                   const float* __restrict__ eb,
                   float* __restrict__ agg) {
    constexpr int D = WPN * 64;        // agg row width
    constexpr int XB = 128;            // x-half bytes per warp (32 lanes x 4B fp16x2)
    constexpr int SLOT = XB + 64;      // + attr
    constexpr int NS = 8;              // ring slots (edges)
    constexpr int LAG = 3;             // lookahead groups (2 edges each)

    __shared__ __align__(16) char s_ring[4 * NS * SLOT];   // 6 KB

    const int tid = threadIdx.x;
    const int lane = tid & 31;
    const int wIn = tid >> 5;
    char* ring = s_ring + wIn * (NS * SLOT);

    const int gw = (blockIdx.x * blockDim.x + tid) >> 5;
    const int n = gw / WPN;
    const int half = gw - n * WPN;
    if (n >= NN) return;
    const int col = half * 64 + lane * 2;

    // weights in registers: 16 f32x2 words
    unsigned long long wp[16];
#pragma unroll
    for (int k = 0; k < 16; k++)
        wp[k] = packf2(eW[k * D + col], eW[k * D + col + 1]);
    unsigned long long ebp = packf2(eb[col], eb[col + 1]);

    const int i0 = __ldg(&g_off[n]);
    const int i1 = __ldg(&g_off[n + 1]);

    float acc0, acc1;
    {
        float2 xv = *(const float2*)&xf[(size_t)n * ldf + col];
        acc0 = xv.x; acc1 = xv.y;
    }

    const int T = i1 - i0;
    const int G = (T + 1) >> 1;        // number of 2-edge groups

    auto issue_edge = [&](int pos, int s) {
        if (pos < i1) {
            char* sp = ring + (pos & (NS - 1)) * SLOT;
            const __half* grow = xh + (size_t)s * ldh + col;
            unsigned sx = (unsigned)__cvta_generic_to_shared(sp) + lane * 4;
            asm volatile("cp.async.ca.shared.global [%0], [%1], 4;"
                         :: "r"(sx), "l"(grow));
            if (lane < 4) {
                const float* ga = g_attrs + (size_t)pos * 16 + lane * 4;
                unsigned sa = (unsigned)__cvta_generic_to_shared(sp) + XB + lane * 16;
                asm volatile("cp.async.ca.shared.global [%0], [%1], 16;"
                             :: "r"(sa), "l"(ga));
            }
        }
    };

    auto ld_srcs2 = [&](int g, int& a, int& b) {
        int p = i0 + 2 * g;
        a = (p < i1) ? __ldg(&g_srcs[p]) : 0;
        b = (p + 1 < i1) ? __ldg(&g_srcs[p + 1]) : 0;
    };

    auto process = [&](int pos) {
        const char* sp = ring + (pos & (NS - 1)) * SLOT;
        const float4* ap = (const float4*)(sp + XB);
        float4 A0 = ap[0], A1 = ap[1], A2 = ap[2], A3 = ap[3];
        float av[16] = {A0.x, A0.y, A0.z, A0.w, A1.x, A1.y, A1.z, A1.w,
                        A2.x, A2.y, A2.z, A2.w, A3.x, A3.y, A3.z, A3.w};
        unsigned long long e = ebp;
#pragma unroll
        for (int k = 0; k < 16; k++) fma2(e, dupf2(av[k]), wp[k]);
        float lo, hi;
        unpackf2(e, lo, hi);
        __half2 xh2 = *(const __half2*)(sp + lane * 4);
        float2 xr = __half22float2(xh2);
        float m0 = xr.x + lo;
        float m1 = xr.y + hi;
        acc0 += m0 > 0.f ? m0 : 0.f;
        acc1 += m1 > 0.f ? m1 : 0.f;
    };

    // prologue: issue LAG groups
    int sA, sB;
#pragma unroll
    for (int j = 0; j < LAG; j++) {
        ld_srcs2(j, sA, sB);
        issue_edge(i0 + 2 * j, sA);
        issue_edge(i0 + 2 * j + 1, sB);
        asm volatile("cp.async.commit_group;" ::: "memory");
    }
    ld_srcs2(LAG, sA, sB);             // srcs for next group to issue

    for (int g = 0; g < G; g++) {
        int nA, nB;
        ld_srcs2(g + LAG + 1, nA, nB); // prefetch next group's srcs
        int p = i0 + 2 * (g + LAG);
        issue_edge(p, sA);
        issue_edge(p + 1, sB);
        asm volatile("cp.async.commit_group;" ::: "memory");
        sA = nA; sB = nB;

        asm volatile("cp.async.wait_group 3;" ::: "memory");
        __syncwarp();

        int q = i0 + 2 * g;
        process(q);
        if (q + 1 < i1) process(q + 1);
    }

    *(float2*)&g_agg[(size_t)n * D + col] = make_float2(acc0, acc1);
}

// ---------------------------------------------------------------------------
// Split-bf16 tensor-core GEMM with pre-converted packed B.
// Optionally writes an fp16 mirror of the output (ld 128) for the next gather.
// ---------------------------------------------------------------------------
__device__ __forceinline__ void mma_bf16(float* acc, const unsigned* a, const unsigned* b) {
    asm volatile(
        "mma.sync.aligned.m16n8k16.row.col.f32.bf16.bf16.f32 "
        "{%0,%1,%2,%3}, {%4,%5,%6,%7}, {%8,%9}, {%0,%1,%2,%3};"
        : "+f"(acc[0]), "+f"(acc[1]), "+f"(acc[2]), "+f"(acc[3])
        : "r"(a[0]), "r"(a[1]), "r"(a[2]), "r"(a[3]), "r"(b[0]), "r"(b[1]));
}

template <int ACT>
__global__ __launch_bounds__(256)
void bf16_gemm(const float* __restrict__ A, int lda,
               const unsigned* __restrict__ PBh,
               const unsigned* __restrict__ PBl,
               const float* __restrict__ bias,
               const float* __restrict__ gamma,
               const float* __restrict__ beta,
               float* __restrict__ Cmat, int ldc,
               __half* __restrict__ Hmir,
               int Nrows, int K, int M, float bn_inv) {
    __shared__ unsigned sAh[128][9];
    __shared__ unsigned sAl[128][9];
    __shared__ unsigned sBh[128][9];
    __shared__ unsigned sBl[128][9];

    const int tid = threadIdx.x;
    const int lane = tid & 31;
    const int wid = tid >> 5;
    const int wm = (wid & 1) * 64;
    const int wn = (wid >> 1) * 32;
    const int row0 = blockIdx.y * 128;
    const int col0 = blockIdx.x * 128;

    float acc[16][4];
#pragma unroll
    for (int i = 0; i < 16; i++)
#pragma unroll
        for (int j = 0; j < 4; j++) acc[i][j] = 0.f;

    float4 ga[2];
    uint2 gh[2], gl[2];

    auto load_tile = [&](int k0) {
#pragma unroll
        for (int j = 0; j < 2; j++) {
            int idx = j * 256 + tid;
            int m = idx >> 2, kk = (idx & 3) << 2;
            int r = row0 + m;
            ga[j] = make_float4(0.f, 0.f, 0.f, 0.f);
            if (r < Nrows) ga[j] = *(const float4*)&A[(size_t)r * lda + k0 + kk];
            int n = (idx & 63) << 1, bkp = idx >> 6;
            size_t off = (size_t)(k0 / 2 + bkp) * M + col0 + n;
            gh[j] = *(const uint2*)&PBh[off];
            gl[j] = *(const uint2*)&PBl[off];
        }
    };

    load_tile(0);

    for (int k0 = 0; k0 < K; k0 += 16) {
        __syncthreads();
#pragma unroll
        for (int j = 0; j < 2; j++) {
            int idx = j * 256 + tid;
            int m = idx >> 2, kp = (idx & 3) << 1;
            float4 v = ga[j];
            float hx = __bfloat162float(__float2bfloat16(v.x));
            float hy = __bfloat162float(__float2bfloat16(v.y));
            float hz = __bfloat162float(__float2bfloat16(v.z));
            float hw = __bfloat162float(__float2bfloat16(v.w));
            sAh[m][kp]     = pack_bf16(hx, hy);
            sAh[m][kp + 1] = pack_bf16(hz, hw);
            sAl[m][kp]     = pack_bf16(v.x - hx, v.y - hy);
            sAl[m][kp + 1] = pack_bf16(v.z - hz, v.w - hw);

            int n = (idx & 63) << 1, bkp = idx >> 6;
            sBh[n][bkp]     = gh[j].x;
            sBh[n + 1][bkp] = gh[j].y;
            sBl[n][bkp]     = gl[j].x;
            sBl[n + 1][bkp] = gl[j].y;
        }
        __syncthreads();

        if (k0 + 16 < K) load_tile(k0 + 16);

        unsigned af[4][4], bh[4][2], bl[4][2];
        const int ar = lane >> 2, ak = lane & 3;
#pragma unroll
        for (int i = 0; i < 4; i++) {
            int m = wm + i * 16 + ar;
            af[i][0] = sAh[m][ak];
            af[i][1] = sAh[m + 8][ak];
            af[i][2] = sAh[m][ak + 4];
            af[i][3] = sAh[m + 8][ak + 4];
        }
#pragma unroll
        for (int j = 0; j < 4; j++) {
            int nn = wn + j * 8 + (lane >> 2);
            bh[j][0] = sBh[nn][lane & 3];
            bh[j][1] = sBh[nn][(lane & 3) + 4];
            bl[j][0] = sBl[nn][lane & 3];
            bl[j][1] = sBl[nn][(lane & 3) + 4];
        }
#pragma unroll
        for (int i = 0; i < 4; i++)
#pragma unroll
            for (int j = 0; j < 4; j++) mma_bf16(acc[i * 4 + j], af[i], bh[j]);
#pragma unroll
        for (int i = 0; i < 4; i++)
#pragma unroll
            for (int j = 0; j < 4; j++) mma_bf16(acc[i * 4 + j], af[i], bl[j]);
#pragma unroll
        for (int i = 0; i < 4; i++) {
            int m = wm + i * 16 + ar;
            af[i][0] = sAl[m][ak];
            af[i][1] = sAl[m + 8][ak];
            af[i][2] = sAl[m][ak + 4];
            af[i][3] = sAl[m + 8][ak + 4];
        }
#pragma unroll
        for (int i = 0; i < 4; i++)
#pragma unroll
            for (int j = 0; j < 4; j++) mma_bf16(acc[i * 4 + j], af[i], bh[j]);
    }

    // epilogue
#pragma unroll
    for (int i = 0; i < 4; i++) {
#pragma unroll
        for (int j = 0; j < 4; j++) {
            int r = row0 + wm + i * 16 + (lane >> 2);
            int c = col0 + wn + j * 8 + (lane & 3) * 2;
            float* ap = acc[i * 4 + j];
#pragma unroll
            for (int h = 0; h < 2; h++) {
                int rr = r + h * 8;
                if (rr >= Nrows) continue;
                float v0 = ap[h * 2 + 0] + bias[c];
                float v1 = ap[h * 2 + 1] + bias[c + 1];
                if (gamma != nullptr) {
                    v0 = gamma[c] * (v0 * bn_inv) + beta[c];
                    v1 = gamma[c + 1] * (v1 * bn_inv) + beta[c + 1];
                }
                if (ACT == 1) { v0 = leaky1(v0); v1 = leaky1(v1); }
                else if (ACT == 2) { v0 = dleaky(v0); v1 = dleaky(v1); }
                *(float2*)&Cmat[(size_t)rr * ldc + c] = make_float2(v0, v1);
                if (Hmir != nullptr)
                    *(__half2*)&Hmir[(size_t)rr * 128 + c] = __floats2half2_rn(v0, v1);
            }
        }
    }
}

// ---------------------------------------------------------------------------
// Pooling
// ---------------------------------------------------------------------------
__global__ void zero_pool_kernel() {
    int idx = blockIdx.x * blockDim.x + threadIdx.x;
    if (idx < NMOL * 128 / 4)
        *(float4*)&g_pool[idx * 4] = make_float4(0.f, 0.f, 0.f, 0.f);
}

__global__ void pool_kernel(const int* __restrict__ batch) {
    int idx = blockIdx.x * blockDim.x + threadIdx.x;
    int n = idx >> 5;
    if (n >= NN) return;
    int c4 = (idx & 31) << 2;
    float4 v = *(const float4*)&g_HS[(size_t)n * HSW + 384 + c4];
    float* p = g_pool + (size_t)batch[n] * 128 + c4;
    asm volatile("red.global.add.v4.f32 [%0], {%1,%2,%3,%4};"
                 :: "l"(p), "f"(v.x), "f"(v.y), "f"(v.z), "f"(v.w) : "memory");
}

__global__ void bcast_kernel(const int* __restrict__ batch) {
    int idx = blockIdx.x * blockDim.x + threadIdx.x;
    int n = idx >> 5;
    if (n >= NN) return;
    int c4 = (idx & 31) << 2;
    float4 v = *(const float4*)&g_pool[(size_t)batch[n] * 128 + c4];
    *(float4*)&g_HS[(size_t)n * HSW + 512 + c4] = v;
}

// ---------------------------------------------------------------------------
// Final: out[n] = sigmoid(Z1[n,:] . fW + fb)
// ---------------------------------------------------------------------------
__global__ void final_kernel(const float* __restrict__ Z,
                             const float* __restrict__ fW,
                             const float* __restrict__ fb,
                             float* __restrict__ out) {
    int idx = blockIdx.x * blockDim.x + threadIdx.x;
    int n = idx >> 5;
    if (n >= NN) return;
    int lane = idx & 31;
    float s = 0.f;
#pragma unroll
    for (int j = lane; j < CLSD; j += 32)
        s = fmaf(Z[(size_t)n * CLSD + j], fW[j], s);
#pragma unroll
    for (int o = 16; o; o >>= 1) s += __shfl_xor_sync(0xffffffffu, s, o);
    if (lane == 0) {
        float z = s + fb[0];
        out[n] = 1.f / (1.f + expf(-z));
    }
}

// ---------------------------------------------------------------------------
// Launch
// ---------------------------------------------------------------------------
extern "C" void kernel_launch(void* const* d_in, const int* in_sizes, int n_in,
                              void* d_out, int out_size) {
    const float* x    = (const float*)d_in[0];
    const int*   ei   = (const int*)d_in[1];
    const float* attr = (const float*)d_in[2];
    const int*   batch= (const int*)d_in[3];
    const float* c1W  = (const float*)d_in[4];
    const float* c1b  = (const float*)d_in[5];
    const float* c1g  = (const float*)d_in[6];
    const float* c1be = (const float*)d_in[7];
    const float* c1eW = (const float*)d_in[8];
    const float* c1eb = (const float*)d_in[9];
    const float* cW   = (const float*)d_in[10];
    const float* cb   = (const float*)d_in[11];
    const float* cg   = (const float*)d_in[12];
    const float* cbe  = (const float*)d_in[13];
    const float* ceW  = (const float*)d_in[14];
    const float* ceb  = (const float*)d_in[15];
    const float* k1W  = (const float*)d_in[16];
    const float* k1b  = (const float*)d_in[17];
    const float* kW   = (const float*)d_in[18];
    const float* kb   = (const float*)d_in[19];
    const float* fW   = (const float*)d_in[20];
    const float* fb   = (const float*)d_in[21];
    float* out = (float*)d_out;

    const int* srcp = ei;
    const int* dstp = ei + EE;

    const float bn_inv = (float)(1.0 / (double)((float)sqrt(1.0 + 1e-5)));

    float *agg, *h0, *HS, *z1, *z2;
    unsigned *Bh, *Bl;
    __half* xh;
    cudaGetSymbolAddress((void**)&agg, g_agg);
    cudaGetSymbolAddress((void**)&h0,  g_h0);
    cudaGetSymbolAddress((void**)&HS,  g_HS);
    cudaGetSymbolAddress((void**)&z1,  g_z1);
    cudaGetSymbolAddress((void**)&z2,  g_z2);
    cudaGetSymbolAddress((void**)&Bh,  g_Bh);
    cudaGetSymbolAddress((void**)&Bl,  g_Bl);
    cudaGetSymbolAddress((void**)&xh,  g_xh);

    // ---- CSR build + weight conversion + fp16 input mirror ----
    wcvt_count_kernel<<<CNT_BLK + WCVT_BLK, 256>>>(dstp, c1W, cW, k1W, kW);
    csr_scan_kernel<<<1, 1024>>>();
    fill_permute_kernel<<<(EE * 4 + 255) / 256, 256>>>(srcp, dstp, attr);
    x2h_kernel<<<(NN * 32 + 255) / 256, 256>>>(x);

    // ---- conv1 (64 -> 128): 1 warp per node; GEMM writes fp16 mirror ----
    {
        gather_kernel<1><<<(NN + 3) / 4, 128>>>(xh, 64, x, INRR, c1eW, c1eb, agg);
        dim3 grid(1, (NN + 127) / 128);
        bf16_gemm<2><<<grid, 256>>>(agg, 64, Bh + WC1_OFF, Bl + WC1_OFF,
                                    c1b, c1g, c1be, h0, 128, xh,
                                    NN, 64, 128, bn_inv);
    }

    // ---- conv loop (4 layers, 128 -> 128): 2 warps per node ----
    for (int i = 0; i < 4; i++) {
        const float* inPtr = (i == 0) ? h0 : (HS + (size_t)(i - 1) * 128);
        int ldin = (i == 0) ? 128 : HSW;
        gather_kernel<2><<<(NN * 2 + 3) / 4, 128>>>(xh, 128, inPtr, ldin,
                                                   ceW + (size_t)i * EDD * OUTD,
                                                   ceb + (size_t)i * OUTD, agg);
        dim3 grid(1, (NN + 127) / 128);
        bf16_gemm<2><<<grid, 256>>>(agg, 128,
                                    Bh + WCV_OFF + (size_t)i * 8192,
                                    Bl + WCV_OFF + (size_t)i * 8192,
                                    cb + (size_t)i * OUTD,
                                    cg + (size_t)i * OUTD,
                                    cbe + (size_t)i * OUTD,
                                    HS + (size_t)i * 128, HSW,
                                    (i < 3) ? xh : (__half*)nullptr,
                                    NN, 128, 128, bn_inv);
    }

    // ---- global_add_pool + broadcast ----
    zero_pool_kernel<<<(NMOL * 128 / 4 + 255) / 256, 256>>>();
    pool_kernel<<<(NN * 32 + 255) / 256, 256>>>(batch);
    bcast_kernel<<<(NN * 32 + 255) / 256, 256>>>(batch);

    // ---- classifier ----
    {
        dim3 grid1(CLSD / 128, (NN + 127) / 128);
        bf16_gemm<0><<<grid1, 256>>>(HS, HSW, Bh + WK1_OFF, Bl + WK1_OFF,
                                     k1b, nullptr, nullptr,
                                     z1, CLSD, (__half*)nullptr, NN, HSW, CLSD, bn_inv);
        bf16_gemm<1><<<grid1, 256>>>(z1, CLSD, Bh + WK2_OFF, Bl + WK2_OFF,
                                     kb, nullptr, nullptr,
                                     z2, CLSD, (__half*)nullptr, NN, CLSD, CLSD, bn_inv);
        bf16_gemm<1><<<grid1, 256>>>(z2, CLSD, Bh + WK3_OFF, Bl + WK3_OFF,
                                     kb + CLSD, nullptr, nullptr,
                                     z1, CLSD, (__half*)nullptr, NN, CLSD, CLSD, bn_inv);
    }

    // ---- final dot + sigmoid ----
    final_kernel<<<(NN * 32 + 255) / 256, 256>>>(z1, fW, fb, out);
}